// round 7
// baseline (speedup 1.0000x reference)
#include <cuda_runtime.h>
#include <cuda_fp16.h>
#include <cstdint>
#include <math_constants.h>

// ============================================================================
// QKV_Attention via mma.sync m16n8k16 fp16 (f32 acc) + ldmatrix.
// Round 7: CTA tile 128x256, warp tile 64x64 (32 HMMA per 8 LDSM), BK=64,
// 3-stage cp.async pipeline, 1 CTA/SM.
// ============================================================================

#define NTHREADS 256
#define BK 64
#define ATILEB 16384                 // 128 rows x 128B
#define BTILEB 32768                 // 256 rows x 128B
#define STAGEB (ATILEB + BTILEB)     // 49152
#define NSTAGE 3
#define DSMEMB (NSTAGE*STAGEB)       // 147456

__device__ __half g_qh [4096UL*4096UL];      // 32 MB
__device__ __half g_xh [4UL*1024UL*512UL];   //  4 MB
__device__ __half g_wh [4096UL*512UL];       //  4 MB
__device__ __half g_xth[4UL*512UL*1024UL];   //  4 MB
__device__ __half g_ph [32768UL*1024UL];     // 64 MB

// ---------------------------------------------------------------- helpers
__device__ __forceinline__ uint32_t smem_u32(const void* p) {
    uint32_t a;
    asm("{ .reg .u64 t; cvta.to.shared.u64 t, %1; cvt.u32.u64 %0, t; }"
        : "=r"(a) : "l"(p));
    return a;
}
#define CP16(d, s) \
    asm volatile("cp.async.cg.shared.global [%0], [%1], 16;" :: "r"(d), "l"(s))
#define CP_COMMIT() asm volatile("cp.async.commit_group;" ::: "memory")
#define CP_WAIT1()  asm volatile("cp.async.wait_group 1;" ::: "memory")

#define LDSM4(r, a) \
    asm volatile("ldmatrix.sync.aligned.m8n8.x4.shared.b16 {%0,%1,%2,%3}, [%4];" \
        : "=r"((r)[0]), "=r"((r)[1]), "=r"((r)[2]), "=r"((r)[3]) : "r"(a))

__device__ __forceinline__ void mma_f16(float c[4], const uint32_t a[4],
                                        uint32_t b0, uint32_t b1) {
    asm volatile(
        "mma.sync.aligned.m16n8k16.row.col.f32.f16.f16.f32 "
        "{%0,%1,%2,%3}, {%4,%5,%6,%7}, {%8,%9}, {%0,%1,%2,%3};"
        : "+f"(c[0]), "+f"(c[1]), "+f"(c[2]), "+f"(c[3])
        : "r"(a[0]), "r"(a[1]), "r"(a[2]), "r"(a[3]), "r"(b0), "r"(b1));
}

// load NROWS rows x 64 fp16 (row stride ld elems) into XOR-swizzled smem tile
template<int NROWS>
__device__ __forceinline__ void load_tile_h(uint32_t dst, const __half* g, int ld, int tid) {
#pragma unroll
    for (int i = 0; i < NROWS / 32; i++) {       // NROWS*8/256 chunks per thread
        int idx = tid + i * NTHREADS;
        int row = idx >> 3;
        int c   = idx & 7;
        uint32_t off = (uint32_t)(row << 7) | (uint32_t)(((c ^ (row & 7)) << 4));
        CP16(dst + off, g + (size_t)row * ld + (c << 3));
    }
}

// ============================================================================
// NT GEMM (fp16 in, f32 acc): C[m,n] = alpha * sum_k A[m,k]*B[n,k]
// CTA tile 128x256, 8 warps (2x4), warp tile 64x64, BK=64, 3 stages.
// ============================================================================
__global__ void __launch_bounds__(NTHREADS, 1)
gemm_h(const __half* __restrict__ A, int lda, long sAb, long sAk,
       const __half* __restrict__ B, int ldb, long sBb, long sBk,
       void* __restrict__ Cv, int ldc, long sCb, long sCk,
       int Kdim, float alpha, int Kcnt, int halfOut)
{
    extern __shared__ __half smh[];
    const uint32_t smb = smem_u32(smh);

    const int tid  = threadIdx.x;
    const int wid  = tid >> 5;
    const int lane = tid & 31;
    const int gid  = lane >> 2;
    const int tg   = lane & 3;
    const int warpMoff = (wid >> 2) * 64;   // 0,64
    const int warpNoff = (wid & 3) * 64;    // 0,64,128,192

    const int z  = blockIdx.z;
    const int zb = z / Kcnt;
    const int zk = z - zb * Kcnt;
    const __half* Ab = A + (size_t)zb * sAb + (size_t)zk * sAk + (size_t)(blockIdx.y * 128) * lda;
    const __half* Bb = B + (size_t)zb * sBb + (size_t)zk * sBk + (size_t)(blockIdx.x * 256) * ldb;
    const size_t cOff = (size_t)zb * sCb + (size_t)zk * sCk
                      + (size_t)(blockIdx.y * 128) * ldc + (size_t)(blockIdx.x * 256);

    const int numK = Kdim >> 6;

    float c[4][8][4];
#pragma unroll
    for (int i = 0; i < 4; i++)
#pragma unroll
        for (int j = 0; j < 8; j++)
#pragma unroll
            for (int r = 0; r < 4; r++) c[i][j][r] = 0.0f;

    // fixed per-lane ldmatrix row components
    const int rlA = lane & 15;
    const int hiA = lane >> 4;
    const int rlB = ((lane >> 4) << 3) + (lane & 7);
    const int hiB = (lane >> 3) & 1;

    // ---- prologue: stages 0 and 1
    load_tile_h<128>(smb,          Ab, lda, tid);
    load_tile_h<256>(smb + ATILEB, Bb, ldb, tid);
    CP_COMMIT();
    if (numK > 1) {
        load_tile_h<128>(smb + STAGEB,          Ab + BK, lda, tid);
        load_tile_h<256>(smb + STAGEB + ATILEB, Bb + BK, ldb, tid);
    }
    CP_COMMIT();

    int buf = 0;
    for (int kt = 0; kt < numK; kt++) {
        CP_WAIT1();
        __syncthreads();

        const int nk = kt + 2;
        if (nk < numK) {
            int nbuf = buf + 2; if (nbuf >= NSTAGE) nbuf -= NSTAGE;
            const uint32_t nbb = smb + nbuf * STAGEB;
            load_tile_h<128>(nbb,          Ab + nk * BK, lda, tid);
            load_tile_h<256>(nbb + ATILEB, Bb + nk * BK, ldb, tid);
        }
        CP_COMMIT();

        const uint32_t At = smb + buf * STAGEB;
        const uint32_t Bt = At + ATILEB;

#pragma unroll
        for (int kk = 0; kk < 4; kk++) {
            uint32_t a[4][4], bb[4][4];
            const int cA = kk * 2 + hiA;
            const int cB = kk * 2 + hiB;
#pragma unroll
            for (int i = 0; i < 4; i++) {
                const int row = warpMoff + i * 16 + rlA;
                uint32_t ad = At + ((uint32_t)row << 7)
                            + (uint32_t)(((cA ^ (row & 7)) << 4));
                LDSM4(a[i], ad);
            }
#pragma unroll
            for (int j = 0; j < 4; j++) {
                const int row = warpNoff + j * 16 + rlB;
                uint32_t bd = Bt + ((uint32_t)row << 7)
                            + (uint32_t)(((cB ^ (row & 7)) << 4));
                LDSM4(bb[j], bd);
            }
#pragma unroll
            for (int i = 0; i < 4; i++)
#pragma unroll
                for (int jj = 0; jj < 8; jj++)
                    mma_f16(c[i][jj], a[i], bb[jj >> 1][(jj & 1) * 2],
                                             bb[jj >> 1][(jj & 1) * 2 + 1]);
        }

        if (++buf == NSTAGE) buf = 0;
    }

    // ---- epilogue
    if (halfOut) {
        __half* Cb = (__half*)Cv + cOff;
#pragma unroll
        for (int i = 0; i < 4; i++) {
            const int r0 = warpMoff + i * 16 + gid;
#pragma unroll
            for (int jj = 0; jj < 8; jj++) {
                const int cc = warpNoff + jj * 8 + tg * 2;
                *(__half2*)(Cb + (size_t)r0 * ldc + cc) =
                    __floats2half2_rn(alpha * c[i][jj][0], alpha * c[i][jj][1]);
                *(__half2*)(Cb + (size_t)(r0 + 8) * ldc + cc) =
                    __floats2half2_rn(alpha * c[i][jj][2], alpha * c[i][jj][3]);
            }
        }
    } else {
        float* Cb = (float*)Cv + cOff;
#pragma unroll
        for (int i = 0; i < 4; i++) {
            const int r0 = warpMoff + i * 16 + gid;
#pragma unroll
            for (int jj = 0; jj < 8; jj++) {
                const int cc = warpNoff + jj * 8 + tg * 2;
                float2 v0, v1;
                v0.x = alpha * c[i][jj][0]; v0.y = alpha * c[i][jj][1];
                v1.x = alpha * c[i][jj][2]; v1.y = alpha * c[i][jj][3];
                *(float2*)(Cb + (size_t)r0 * ldc + cc)       = v0;
                *(float2*)(Cb + (size_t)(r0 + 8) * ldc + cc) = v1;
            }
        }
    }
}

// ============================================================================
// prep: f32 -> fp16
// ============================================================================
__global__ void cvt_h(const float* __restrict__ in, __half* __restrict__ out, int n4)
{
    int i = blockIdx.x * blockDim.x + threadIdx.x;
    if (i >= n4) return;
    float4 v = ((const float4*)in)[i];
    ((__half2*)out)[2 * i]     = __floats2half2_rn(v.x, v.y);
    ((__half2*)out)[2 * i + 1] = __floats2half2_rn(v.z, v.w);
}

// transpose xsa (b,1024,512) f32 -> g_xth (b,512,1024) fp16
__global__ void transpose_h(const float* __restrict__ in, __half* __restrict__ out)
{
    __shared__ float t[32][33];
    const int b = blockIdx.z;
    const int l0 = blockIdx.x * 32, e0 = blockIdx.y * 32;
    in  += (size_t)b * 524288;
    out += (size_t)b * 524288;
    const int x = threadIdx.x, y = threadIdx.y;  // 32 x 8
#pragma unroll
    for (int i = 0; i < 32; i += 8)
        t[y + i][x] = in[(size_t)(l0 + y + i) * 512 + e0 + x];
    __syncthreads();
#pragma unroll
    for (int i = 0; i < 32; i += 8)
        out[(size_t)(e0 + y + i) * 1024 + l0 + x] = __float2half_rn(t[x][y + i]);
}

// ============================================================================
// softmax rows of 1024, in place (f32); also writes fp16 copy to ph
// ============================================================================
__global__ void softmax_rows_kernel(float* __restrict__ p, __half* __restrict__ ph)
{
    __shared__ float red[32];
    const size_t roff = (size_t)blockIdx.x * 1024;
    float* row = p + roff;
    const int t = threadIdx.x;

    float4 v = ((const float4*)row)[t];

    float m = fmaxf(fmaxf(v.x, v.y), fmaxf(v.z, v.w));
#pragma unroll
    for (int o = 16; o; o >>= 1) m = fmaxf(m, __shfl_xor_sync(0xffffffffu, m, o));
    if ((t & 31) == 0) red[t >> 5] = m;
    __syncthreads();
    if (t < 32) {
        float mm = (t < 8) ? red[t] : -CUDART_INF_F;
#pragma unroll
        for (int o = 4; o; o >>= 1) mm = fmaxf(mm, __shfl_xor_sync(0xffffffffu, mm, o));
        if (t == 0) red[0] = mm;
    }
    __syncthreads();
    m = red[0];
    __syncthreads();

    v.x = __expf(v.x - m); v.y = __expf(v.y - m);
    v.z = __expf(v.z - m); v.w = __expf(v.w - m);

    float s = v.x + v.y + v.z + v.w;
#pragma unroll
    for (int o = 16; o; o >>= 1) s += __shfl_xor_sync(0xffffffffu, s, o);
    if ((t & 31) == 0) red[t >> 5] = s;
    __syncthreads();
    if (t < 32) {
        float ss = (t < 8) ? red[t] : 0.0f;
#pragma unroll
        for (int o = 4; o; o >>= 1) ss += __shfl_xor_sync(0xffffffffu, ss, o);
        if (t == 0) red[0] = ss;
    }
    __syncthreads();
    const float inv = 1.0f / red[0];

    v.x *= inv; v.y *= inv; v.z *= inv; v.w *= inv;
    ((float4*)row)[t] = v;

    __half2* pp = (__half2*)(ph + roff);
    pp[2 * t]     = __floats2half2_rn(v.x, v.y);
    pp[2 * t + 1] = __floats2half2_rn(v.z, v.w);
}

// ============================================================================
extern "C" void kernel_launch(void* const* d_in, const int* in_sizes, int n_in,
                              void* d_out, int out_size)
{
    (void)in_sizes; (void)n_in; (void)out_size;
    const float* xsa = (const float*)d_in[0];   // (4,1024,512)
    const float* Wq  = (const float*)d_in[1];   // (4096,512)
    float* out  = (float*)d_out;
    float* xid  = out;                          // 16777216 floats
    float* pijk = out + 16777216UL;             // 33554432 floats

    __half *qh, *xh, *wh, *xth, *ph;
    cudaGetSymbolAddress((void**)&qh,  g_qh);
    cudaGetSymbolAddress((void**)&xh,  g_xh);
    cudaGetSymbolAddress((void**)&wh,  g_wh);
    cudaGetSymbolAddress((void**)&xth, g_xth);
    cudaGetSymbolAddress((void**)&ph,  g_ph);

    cudaFuncSetAttribute(gemm_h, cudaFuncAttributeMaxDynamicSharedMemorySize, DSMEMB);

    const float inv_sqrt_e = 0.044194173824159216f;  // 1/sqrt(512)

    // prep
    cvt_h<<<2048, 256>>>(xsa, xh, 524288);
    cvt_h<<<2048, 256>>>(Wq,  wh, 524288);
    transpose_h<<<dim3(32, 16, 4), dim3(32, 8)>>>(xsa, xth);

    // K1: q = xh @ wh^T   M=4096 N=4096 K=512, fp16 out
    gemm_h<<<dim3(16, 32, 1), NTHREADS, DSMEMB>>>(
        xh, 512, 0, 0,
        wh, 512, 0, 0,
        qh, 4096, 0, 0,
        512, 1.0f, 1, 1);

    // K2: logits = qh_bk @ xh_b^T / sqrt(E)   M=1024 N=1024 K=512, 32 batches
    gemm_h<<<dim3(4, 8, 32), NTHREADS, DSMEMB>>>(
        qh, 4096, 4194304L, 512L,
        xh, 512,  524288L,  0L,
        pijk, 8192, 8388608L, 1024L,
        512, inv_sqrt_e, 8, 0);

    // K3: softmax -> pijk f32 (output) + ph fp16 (K4 operand)
    softmax_rows_kernel<<<32768, 256>>>(pijk, ph);

    // K4: y = ph_bk @ xth_b^T   M=1024 N=512 K=1024, 32 batches
    // ph layout (b,l,k,m): row stride 8192, k stride 1024
    gemm_h<<<dim3(2, 8, 32), NTHREADS, DSMEMB>>>(
        ph,  8192, 8388608L, 1024L,
        xth, 1024, 524288L,  0L,
        xid, 4096, 4194304L, 512L,
        1024, 1.0f, 8, 0);
}

// round 8
// speedup vs baseline: 1.0089x; 1.0089x over previous
#include <cuda_runtime.h>
#include <cuda_fp16.h>
#include <cstdint>
#include <math_constants.h>

// ============================================================================
// QKV_Attention via mma.sync m16n8k16 fp16 (f32 acc) + ldmatrix.
// Round 8: CTA tile 256x128, 512 threads (16 warps, 4x4), warp tile 64x32,
// BK=64, 3-stage cp.async pipeline. Cuts smem B/cyc demand under the 128 B/cyc
// crossbar (round-6 shape demanded 160 B/cyc -> 80% tensor cap).
// ============================================================================

#define NTHREADS 512
#define BK 64
#define ATILEB 32768                 // 256 rows x 128B
#define BTILEB 16384                 // 128 rows x 128B
#define STAGEB (ATILEB + BTILEB)     // 49152
#define NSTAGE 3
#define DSMEMB (NSTAGE*STAGEB)       // 147456

__device__ __half g_qh [4096UL*4096UL];      // 32 MB
__device__ __half g_xh [4UL*1024UL*512UL];   //  4 MB
__device__ __half g_wh [4096UL*512UL];       //  4 MB
__device__ __half g_xth[4UL*512UL*1024UL];   //  4 MB
__device__ __half g_ph [32768UL*1024UL];     // 64 MB

// ---------------------------------------------------------------- helpers
__device__ __forceinline__ uint32_t smem_u32(const void* p) {
    uint32_t a;
    asm("{ .reg .u64 t; cvta.to.shared.u64 t, %1; cvt.u32.u64 %0, t; }"
        : "=r"(a) : "l"(p));
    return a;
}
#define CP16(d, s) \
    asm volatile("cp.async.cg.shared.global [%0], [%1], 16;" :: "r"(d), "l"(s))
#define CP_COMMIT() asm volatile("cp.async.commit_group;" ::: "memory")
#define CP_WAIT1()  asm volatile("cp.async.wait_group 1;" ::: "memory")

#define LDSM4(r, a) \
    asm volatile("ldmatrix.sync.aligned.m8n8.x4.shared.b16 {%0,%1,%2,%3}, [%4];" \
        : "=r"((r)[0]), "=r"((r)[1]), "=r"((r)[2]), "=r"((r)[3]) : "r"(a))

__device__ __forceinline__ void mma_f16(float c[4], const uint32_t a[4],
                                        uint32_t b0, uint32_t b1) {
    asm volatile(
        "mma.sync.aligned.m16n8k16.row.col.f32.f16.f16.f32 "
        "{%0,%1,%2,%3}, {%4,%5,%6,%7}, {%8,%9}, {%0,%1,%2,%3};"
        : "+f"(c[0]), "+f"(c[1]), "+f"(c[2]), "+f"(c[3])
        : "r"(a[0]), "r"(a[1]), "r"(a[2]), "r"(a[3]), "r"(b0), "r"(b1));
}

// load NROWS rows x 64 fp16 (row stride ld elems) into XOR-swizzled smem tile
template<int NROWS>
__device__ __forceinline__ void load_tile_h(uint32_t dst, const __half* g, int ld, int tid) {
#pragma unroll
    for (int i = 0; i < (NROWS * 8) / NTHREADS; i++) {
        int idx = tid + i * NTHREADS;
        int row = idx >> 3;
        int c   = idx & 7;
        uint32_t off = (uint32_t)(row << 7) | (uint32_t)(((c ^ (row & 7)) << 4));
        CP16(dst + off, g + (size_t)row * ld + (c << 3));
    }
}

// ============================================================================
// NT GEMM (fp16 in, f32 acc): C[m,n] = alpha * sum_k A[m,k]*B[n,k]
// CTA tile 256x128, 16 warps (4x4), warp tile 64x32, BK=64, 3 stages.
// ============================================================================
__global__ void __launch_bounds__(NTHREADS, 1)
gemm_h(const __half* __restrict__ A, int lda, long sAb, long sAk,
       const __half* __restrict__ B, int ldb, long sBb, long sBk,
       void* __restrict__ Cv, int ldc, long sCb, long sCk,
       int Kdim, float alpha, int Kcnt, int halfOut)
{
    extern __shared__ __half smh[];
    const uint32_t smb = smem_u32(smh);

    const int tid  = threadIdx.x;
    const int wid  = tid >> 5;
    const int lane = tid & 31;
    const int gid  = lane >> 2;
    const int tg   = lane & 3;
    const int warpMoff = (wid >> 2) * 64;   // 0,64,128,192
    const int warpNoff = (wid & 3) * 32;    // 0,32,64,96

    const int z  = blockIdx.z;
    const int zb = z / Kcnt;
    const int zk = z - zb * Kcnt;
    const __half* Ab = A + (size_t)zb * sAb + (size_t)zk * sAk + (size_t)(blockIdx.y * 256) * lda;
    const __half* Bb = B + (size_t)zb * sBb + (size_t)zk * sBk + (size_t)(blockIdx.x * 128) * ldb;
    const size_t cOff = (size_t)zb * sCb + (size_t)zk * sCk
                      + (size_t)(blockIdx.y * 256) * ldc + (size_t)(blockIdx.x * 128);

    const int numK = Kdim >> 6;

    float c[4][4][4];
#pragma unroll
    for (int i = 0; i < 4; i++)
#pragma unroll
        for (int j = 0; j < 4; j++)
#pragma unroll
            for (int r = 0; r < 4; r++) c[i][j][r] = 0.0f;

    // fixed per-lane ldmatrix row components
    const int rlA = lane & 15;
    const int hiA = lane >> 4;
    const int rlB = ((lane >> 4) << 3) + (lane & 7);
    const int hiB = (lane >> 3) & 1;

    // ---- prologue: stages 0 and 1
    load_tile_h<256>(smb,          Ab, lda, tid);
    load_tile_h<128>(smb + ATILEB, Bb, ldb, tid);
    CP_COMMIT();
    if (numK > 1) {
        load_tile_h<256>(smb + STAGEB,          Ab + BK, lda, tid);
        load_tile_h<128>(smb + STAGEB + ATILEB, Bb + BK, ldb, tid);
    }
    CP_COMMIT();

    int buf = 0;
    for (int kt = 0; kt < numK; kt++) {
        CP_WAIT1();
        __syncthreads();

        const int nk = kt + 2;
        if (nk < numK) {
            int nbuf = buf + 2; if (nbuf >= NSTAGE) nbuf -= NSTAGE;
            const uint32_t nbb = smb + nbuf * STAGEB;
            load_tile_h<256>(nbb,          Ab + nk * BK, lda, tid);
            load_tile_h<128>(nbb + ATILEB, Bb + nk * BK, ldb, tid);
        }
        CP_COMMIT();

        const uint32_t At = smb + buf * STAGEB;
        const uint32_t Bt = At + ATILEB;

#pragma unroll
        for (int kk = 0; kk < 4; kk++) {
            uint32_t a[4][4], bb[2][4];
            const int cA = kk * 2 + hiA;
            const int cB = kk * 2 + hiB;
#pragma unroll
            for (int i = 0; i < 4; i++) {
                const int row = warpMoff + i * 16 + rlA;
                uint32_t ad = At + ((uint32_t)row << 7)
                            + (uint32_t)(((cA ^ (row & 7)) << 4));
                LDSM4(a[i], ad);
            }
#pragma unroll
            for (int j = 0; j < 2; j++) {
                const int row = warpNoff + j * 16 + rlB;
                uint32_t bd = Bt + ((uint32_t)row << 7)
                            + (uint32_t)(((cB ^ (row & 7)) << 4));
                LDSM4(bb[j], bd);
            }
#pragma unroll
            for (int i = 0; i < 4; i++)
#pragma unroll
                for (int jj = 0; jj < 4; jj++)
                    mma_f16(c[i][jj], a[i], bb[jj >> 1][(jj & 1) * 2],
                                             bb[jj >> 1][(jj & 1) * 2 + 1]);
        }

        if (++buf == NSTAGE) buf = 0;
    }

    // ---- epilogue
    if (halfOut) {
        __half* Cb = (__half*)Cv + cOff;
#pragma unroll
        for (int i = 0; i < 4; i++) {
            const int r0 = warpMoff + i * 16 + gid;
#pragma unroll
            for (int jj = 0; jj < 4; jj++) {
                const int cc = warpNoff + jj * 8 + tg * 2;
                *(__half2*)(Cb + (size_t)r0 * ldc + cc) =
                    __floats2half2_rn(alpha * c[i][jj][0], alpha * c[i][jj][1]);
                *(__half2*)(Cb + (size_t)(r0 + 8) * ldc + cc) =
                    __floats2half2_rn(alpha * c[i][jj][2], alpha * c[i][jj][3]);
            }
        }
    } else {
        float* Cb = (float*)Cv + cOff;
#pragma unroll
        for (int i = 0; i < 4; i++) {
            const int r0 = warpMoff + i * 16 + gid;
#pragma unroll
            for (int jj = 0; jj < 4; jj++) {
                const int cc = warpNoff + jj * 8 + tg * 2;
                float2 v0, v1;
                v0.x = alpha * c[i][jj][0]; v0.y = alpha * c[i][jj][1];
                v1.x = alpha * c[i][jj][2]; v1.y = alpha * c[i][jj][3];
                *(float2*)(Cb + (size_t)r0 * ldc + cc)       = v0;
                *(float2*)(Cb + (size_t)(r0 + 8) * ldc + cc) = v1;
            }
        }
    }
}

// ============================================================================
// prep: f32 -> fp16
// ============================================================================
__global__ void cvt_h(const float* __restrict__ in, __half* __restrict__ out, int n4)
{
    int i = blockIdx.x * blockDim.x + threadIdx.x;
    if (i >= n4) return;
    float4 v = ((const float4*)in)[i];
    ((__half2*)out)[2 * i]     = __floats2half2_rn(v.x, v.y);
    ((__half2*)out)[2 * i + 1] = __floats2half2_rn(v.z, v.w);
}

// transpose xsa (b,1024,512) f32 -> g_xth (b,512,1024) fp16
__global__ void transpose_h(const float* __restrict__ in, __half* __restrict__ out)
{
    __shared__ float t[32][33];
    const int b = blockIdx.z;
    const int l0 = blockIdx.x * 32, e0 = blockIdx.y * 32;
    in  += (size_t)b * 524288;
    out += (size_t)b * 524288;
    const int x = threadIdx.x, y = threadIdx.y;  // 32 x 8
#pragma unroll
    for (int i = 0; i < 32; i += 8)
        t[y + i][x] = in[(size_t)(l0 + y + i) * 512 + e0 + x];
    __syncthreads();
#pragma unroll
    for (int i = 0; i < 32; i += 8)
        out[(size_t)(e0 + y + i) * 1024 + l0 + x] = __float2half_rn(t[x][y + i]);
}

// ============================================================================
// softmax rows of 1024, in place (f32); also writes fp16 copy to ph
// ============================================================================
__global__ void softmax_rows_kernel(float* __restrict__ p, __half* __restrict__ ph)
{
    __shared__ float red[32];
    const size_t roff = (size_t)blockIdx.x * 1024;
    float* row = p + roff;
    const int t = threadIdx.x;

    float4 v = ((const float4*)row)[t];

    float m = fmaxf(fmaxf(v.x, v.y), fmaxf(v.z, v.w));
#pragma unroll
    for (int o = 16; o; o >>= 1) m = fmaxf(m, __shfl_xor_sync(0xffffffffu, m, o));
    if ((t & 31) == 0) red[t >> 5] = m;
    __syncthreads();
    if (t < 32) {
        float mm = (t < 8) ? red[t] : -CUDART_INF_F;
#pragma unroll
        for (int o = 4; o; o >>= 1) mm = fmaxf(mm, __shfl_xor_sync(0xffffffffu, mm, o));
        if (t == 0) red[0] = mm;
    }
    __syncthreads();
    m = red[0];
    __syncthreads();

    v.x = __expf(v.x - m); v.y = __expf(v.y - m);
    v.z = __expf(v.z - m); v.w = __expf(v.w - m);

    float s = v.x + v.y + v.z + v.w;
#pragma unroll
    for (int o = 16; o; o >>= 1) s += __shfl_xor_sync(0xffffffffu, s, o);
    if ((t & 31) == 0) red[t >> 5] = s;
    __syncthreads();
    if (t < 32) {
        float ss = (t < 8) ? red[t] : 0.0f;
#pragma unroll
        for (int o = 4; o; o >>= 1) ss += __shfl_xor_sync(0xffffffffu, ss, o);
        if (t == 0) red[0] = ss;
    }
    __syncthreads();
    const float inv = 1.0f / red[0];

    v.x *= inv; v.y *= inv; v.z *= inv; v.w *= inv;
    ((float4*)row)[t] = v;

    __half2* pp = (__half2*)(ph + roff);
    pp[2 * t]     = __floats2half2_rn(v.x, v.y);
    pp[2 * t + 1] = __floats2half2_rn(v.z, v.w);
}

// ============================================================================
extern "C" void kernel_launch(void* const* d_in, const int* in_sizes, int n_in,
                              void* d_out, int out_size)
{
    (void)in_sizes; (void)n_in; (void)out_size;
    const float* xsa = (const float*)d_in[0];   // (4,1024,512)
    const float* Wq  = (const float*)d_in[1];   // (4096,512)
    float* out  = (float*)d_out;
    float* xid  = out;                          // 16777216 floats
    float* pijk = out + 16777216UL;             // 33554432 floats

    __half *qh, *xh, *wh, *xth, *ph;
    cudaGetSymbolAddress((void**)&qh,  g_qh);
    cudaGetSymbolAddress((void**)&xh,  g_xh);
    cudaGetSymbolAddress((void**)&wh,  g_wh);
    cudaGetSymbolAddress((void**)&xth, g_xth);
    cudaGetSymbolAddress((void**)&ph,  g_ph);

    cudaFuncSetAttribute(gemm_h, cudaFuncAttributeMaxDynamicSharedMemorySize, DSMEMB);

    const float inv_sqrt_e = 0.044194173824159216f;  // 1/sqrt(512)

    // prep
    cvt_h<<<2048, 256>>>(xsa, xh, 524288);
    cvt_h<<<2048, 256>>>(Wq,  wh, 524288);
    transpose_h<<<dim3(32, 16, 4), dim3(32, 8)>>>(xsa, xth);

    // K1: q = xh @ wh^T   M=4096 N=4096 K=512, fp16 out
    gemm_h<<<dim3(32, 16, 1), NTHREADS, DSMEMB>>>(
        xh, 512, 0, 0,
        wh, 512, 0, 0,
        qh, 4096, 0, 0,
        512, 1.0f, 1, 1);

    // K2: logits = qh_bk @ xh_b^T / sqrt(E)   M=1024 N=1024 K=512, 32 batches
    gemm_h<<<dim3(8, 4, 32), NTHREADS, DSMEMB>>>(
        qh, 4096, 4194304L, 512L,
        xh, 512,  524288L,  0L,
        pijk, 8192, 8388608L, 1024L,
        512, inv_sqrt_e, 8, 0);

    // K3: softmax -> pijk f32 (output) + ph fp16 (K4 operand)
    softmax_rows_kernel<<<32768, 256>>>(pijk, ph);

    // K4: y = ph_bk @ xth_b^T   M=1024 N=512 K=1024, 32 batches
    // ph layout (b,l,k,m): row stride 8192, k stride 1024
    gemm_h<<<dim3(4, 4, 32), NTHREADS, DSMEMB>>>(
        ph,  8192, 8388608L, 1024L,
        xth, 1024, 524288L,  0L,
        xid, 4096, 4194304L, 512L,
        1024, 1.0f, 8, 0);
}